// round 1
// baseline (speedup 1.0000x reference)
#include <cuda_runtime.h>
#include <cuda_bf16.h>

// ---------------- geometry ----------------
#define L0      512
#define C1_O    508          // 512-4
#define P1_O    254
#define C3_O    250          // 254-4
#define P3_O    125
#define NP3     (16*125*125) // 250000
#define N4P3    (NP3/4)      // 62500 float4
#define F6OUT   98304
#define NOUT    54
#define C5_SPLIT 32
#define FIN_SPLIT 64

// ---------------- scratch (device globals, no allocation) ----------------
__device__ __align__(16) float g_h1[6*C1_O*C1_O];
__device__ __align__(16) float g_p1[6*P1_O*P1_O];
__device__ __align__(16) float g_h3[16*C3_O*C3_O];
__device__ __align__(16) float g_p3[NP3];
__device__ __align__(16) float g_c5part[120*C5_SPLIT];
__device__ __align__(16) float g_c5[120];
__device__ __align__(16) float g_f6[F6OUT];
__device__ __align__(16) float g_fpart[NOUT*FIN_SPLIT];

// ---------------- C1: 5x5 conv + ReLU ----------------
__global__ void k_conv1(const float* __restrict__ x,
                        const float* __restrict__ W1,
                        const float* __restrict__ b1) {
    int idx = blockIdx.x * blockDim.x + threadIdx.x;
    if (idx >= C1_O * C1_O) return;
    int oy = idx / C1_O, ox = idx % C1_O;
    float p[25];
#pragma unroll
    for (int i = 0; i < 5; i++)
#pragma unroll
        for (int j = 0; j < 5; j++)
            p[i*5+j] = x[(oy+i)*L0 + ox + j];
#pragma unroll
    for (int o = 0; o < 6; o++) {
        float acc = b1[o];
#pragma unroll
        for (int k = 0; k < 25; k++)
            acc = fmaf(p[k], W1[o*25 + k], acc);
        g_h1[o*C1_O*C1_O + idx] = fmaxf(acc, 0.0f);
    }
}

// ---------------- 2x2 avg pool (h1 -> p1) ----------------
__global__ void k_pool1() {
    int idx = blockIdx.x * blockDim.x + threadIdx.x;
    if (idx >= 6 * P1_O * P1_O) return;
    int c = idx / (P1_O*P1_O);
    int r = idx % (P1_O*P1_O);
    int y = r / P1_O, xx = r % P1_O;
    const float* base = g_h1 + c*C1_O*C1_O + (2*y)*C1_O + 2*xx;
    g_p1[idx] = 0.25f * (base[0] + base[1] + base[C1_O] + base[C1_O+1]);
}

// ---------------- C3: sparse-masked 5x5 conv + ReLU ----------------
__global__ void k_conv3(const float* __restrict__ W3,
                        const float* __restrict__ b3) {
    __shared__ float sw[16*6*25];
    for (int t = threadIdx.x; t < 16*6*25; t += blockDim.x) sw[t] = W3[t];
    __syncthreads();

    int idx = blockIdx.x * blockDim.x + threadIdx.x;
    if (idx >= C3_O * C3_O) return;
    int oy = idx / C3_O, ox = idx % C3_O;

    const unsigned MASKS[16] = {
        0x07u, 0x0Eu, 0x1Cu, 0x38u, 0x31u, 0x23u,
        0x0Fu, 0x1Eu, 0x3Cu, 0x39u, 0x33u, 0x27u,
        0x1Bu, 0x36u, 0x2Du, 0x3Fu };

    float acc[16];
#pragma unroll
    for (int o = 0; o < 16; o++) acc[o] = b3[o];

#pragma unroll
    for (int c = 0; c < 6; c++) {
        float p[25];
#pragma unroll
        for (int i = 0; i < 5; i++)
#pragma unroll
            for (int j = 0; j < 5; j++)
                p[i*5+j] = g_p1[c*P1_O*P1_O + (oy+i)*P1_O + ox + j];
#pragma unroll
        for (int o = 0; o < 16; o++) {
            if ((MASKS[o] >> c) & 1u) {
                const float* w = &sw[(o*6 + c) * 25];
#pragma unroll
                for (int k = 0; k < 25; k++)
                    acc[o] = fmaf(p[k], w[k], acc[o]);
            }
        }
    }
#pragma unroll
    for (int o = 0; o < 16; o++)
        g_h3[o*C3_O*C3_O + idx] = fmaxf(acc[o], 0.0f);
}

// ---------------- 2x2 avg pool (h3 -> p3) ----------------
__global__ void k_pool3() {
    int idx = blockIdx.x * blockDim.x + threadIdx.x;
    if (idx >= NP3) return;
    int c = idx / (P3_O*P3_O);
    int r = idx % (P3_O*P3_O);
    int y = r / P3_O, xx = r % P3_O;
    const float* base = g_h3 + c*C3_O*C3_O + (2*y)*C3_O + 2*xx;
    g_p3[idx] = 0.25f * (base[0] + base[1] + base[C3_O] + base[C3_O+1]);
}

// ---------------- C5: 120 x dot(250000), split-K partials ----------------
__global__ void k_c5(const float* __restrict__ W5) {
    int o = blockIdx.x;          // 0..119
    int s = blockIdx.y;          // 0..31
    const float4* __restrict__ w = (const float4*)(W5 + (size_t)o * NP3);
    const float4* __restrict__ h = (const float4*)g_p3;
    const int per = (N4P3 + C5_SPLIT - 1) / C5_SPLIT;   // 1954
    int start = s * per;
    int end   = min(start + per, N4P3);
    float acc = 0.0f;
    for (int i = start + threadIdx.x; i < end; i += blockDim.x) {
        float4 a = __ldg(&w[i]);
        float4 b = h[i];
        acc += a.x*b.x + a.y*b.y + a.z*b.z + a.w*b.w;
    }
    __shared__ float red[256];
    red[threadIdx.x] = acc;
    __syncthreads();
#pragma unroll
    for (int st = 128; st > 0; st >>= 1) {
        if (threadIdx.x < st) red[threadIdx.x] += red[threadIdx.x + st];
        __syncthreads();
    }
    if (threadIdx.x == 0) g_c5part[o * C5_SPLIT + s] = red[0];
}

__global__ void k_c5_reduce(const float* __restrict__ b5) {
    int o = threadIdx.x;
    if (o >= 120) return;
    float acc = b5[o];
#pragma unroll
    for (int s = 0; s < C5_SPLIT; s++) acc += g_c5part[o * C5_SPLIT + s];
    g_c5[o] = fmaxf(acc, 0.0f);
}

// ---------------- F6: GEMV 98304x120, warp-per-row ----------------
__global__ void k_f6(const float* __restrict__ W6,
                     const float* __restrict__ b6) {
    __shared__ __align__(16) float sc[120];
    if (threadIdx.x < 120) sc[threadIdx.x] = g_c5[threadIdx.x];
    __syncthreads();

    int warp = threadIdx.x >> 5;
    int lane = threadIdx.x & 31;
    int j = blockIdx.x * 8 + warp;          // block = 256 threads = 8 warps
    // row = 120 floats = 30 float4; lane < 30 loads one float4
    float acc = 0.0f;
    if (lane < 30) {
        float4 a = __ldg((const float4*)(W6 + (size_t)j * 120) + lane);
        float4 b = ((const float4*)sc)[lane];
        acc = a.x*b.x + a.y*b.y + a.z*b.z + a.w*b.w;
    }
#pragma unroll
    for (int off = 16; off > 0; off >>= 1)
        acc += __shfl_down_sync(0xFFFFFFFFu, acc, off);
    if (lane == 0) g_f6[j] = fmaxf(acc + b6[j], 0.0f);
}

// ---------------- final: GEMV 54x98304, split-K partials ----------------
__global__ void k_fin(const float* __restrict__ W7) {
    int o = blockIdx.x;          // 0..53
    int s = blockIdx.y;          // 0..63
    const float4* __restrict__ w = (const float4*)(W7 + (size_t)o * F6OUT);
    const float4* __restrict__ h = (const float4*)g_f6;
    const int n4 = F6OUT / 4;                     // 24576
    const int per = n4 / FIN_SPLIT;               // 384
    int start = s * per;
    float acc = 0.0f;
    for (int i = start + threadIdx.x; i < start + per; i += blockDim.x) {
        float4 a = __ldg(&w[i]);
        float4 b = h[i];
        acc += a.x*b.x + a.y*b.y + a.z*b.z + a.w*b.w;
    }
    __shared__ float red[256];
    red[threadIdx.x] = acc;
    __syncthreads();
#pragma unroll
    for (int st = 128; st > 0; st >>= 1) {
        if (threadIdx.x < st) red[threadIdx.x] += red[threadIdx.x + st];
        __syncthreads();
    }
    if (threadIdx.x == 0) g_fpart[o * FIN_SPLIT + s] = red[0];
}

__global__ void k_fin_reduce(const float* __restrict__ b7, float* __restrict__ out) {
    int o = threadIdx.x;
    if (o >= NOUT) return;
    float acc = b7[o];
#pragma unroll
    for (int s = 0; s < FIN_SPLIT; s++) acc += g_fpart[o * FIN_SPLIT + s];
    out[o] = acc;
}

// ---------------- launch ----------------
extern "C" void kernel_launch(void* const* d_in, const int* in_sizes, int n_in,
                              void* d_out, int out_size) {
    const float* x  = (const float*)d_in[0];
    const float* W1 = (const float*)d_in[1];
    const float* b1 = (const float*)d_in[2];
    const float* W3 = (const float*)d_in[3];
    const float* b3 = (const float*)d_in[4];
    const float* W5 = (const float*)d_in[5];
    const float* b5 = (const float*)d_in[6];
    const float* W6 = (const float*)d_in[7];
    const float* b6 = (const float*)d_in[8];
    const float* W7 = (const float*)d_in[9];
    const float* b7 = (const float*)d_in[10];
    float* out = (float*)d_out;

    k_conv1<<<(C1_O*C1_O + 255)/256, 256>>>(x, W1, b1);
    k_pool1<<<(6*P1_O*P1_O + 255)/256, 256>>>();
    k_conv3<<<(C3_O*C3_O + 255)/256, 256>>>(W3, b3);
    k_pool3<<<(NP3 + 255)/256, 256>>>();
    k_c5<<<dim3(120, C5_SPLIT), 256>>>(W5);
    k_c5_reduce<<<1, 128>>>(b5);
    k_f6<<<F6OUT/8, 256>>>(W6, b6);
    k_fin<<<dim3(NOUT, FIN_SPLIT), 256>>>(W7);
    k_fin_reduce<<<1, 64>>>(b7, out);
}

// round 2
// speedup vs baseline: 1.1228x; 1.1228x over previous
#include <cuda_runtime.h>
#include <cuda_bf16.h>

// ---------------- geometry ----------------
#define L0      512
#define P1_O    254          // pooled conv1 output
#define P3_O    125
#define NP3     (16*125*125) // 250000
#define N4P3    (NP3/4)      // 62500 float4
#define F6OUT   98304
#define NOUT    54
#define C5_SPLIT 32
#define FIN_SPLIT 64

// ---------------- scratch (device globals, no allocation) ----------------
__device__ __align__(16) float g_p1[6*P1_O*P1_O];
__device__ __align__(16) float g_p3[NP3];
__device__ __align__(16) float g_c5part[120*C5_SPLIT];
__device__ __align__(16) float g_c5[120];
__device__ __align__(16) float g_f6[F6OUT];
__device__ __align__(16) float g_fpart[NOUT*FIN_SPLIT];
__device__ int g_c5cnt;   // zero-init; self-resetting
__device__ int g_fincnt;  // zero-init; self-resetting

// ---------------- fused C1 conv 5x5 + ReLU + 2x2 avgpool ----------------
__global__ void k_c1p1(const float* __restrict__ x,
                       const float* __restrict__ W1,
                       const float* __restrict__ b1) {
    __shared__ float sw[6*25];
    __shared__ float sb[6];
    if (threadIdx.x < 150) sw[threadIdx.x] = W1[threadIdx.x];
    if (threadIdx.x < 6)   sb[threadIdx.x] = b1[threadIdx.x];
    __syncthreads();

    int idx = blockIdx.x * blockDim.x + threadIdx.x;
    if (idx >= P1_O * P1_O) return;
    int py = idx / P1_O, px = idx % P1_O;

    // 6x6 input patch covering the 4 conv taps feeding this pooled pixel
    float p[36];
#pragma unroll
    for (int i = 0; i < 6; i++)
#pragma unroll
        for (int j = 0; j < 6; j++)
            p[i*6+j] = x[(2*py + i)*L0 + 2*px + j];

#pragma unroll
    for (int o = 0; o < 6; o++) {
        float b = sb[o];
        float a00 = b, a01 = b, a10 = b, a11 = b;
#pragma unroll
        for (int i = 0; i < 5; i++)
#pragma unroll
            for (int j = 0; j < 5; j++) {
                float w = sw[o*25 + i*5 + j];
                a00 = fmaf(p[ i   *6 + j    ], w, a00);
                a01 = fmaf(p[ i   *6 + j + 1], w, a01);
                a10 = fmaf(p[(i+1)*6 + j    ], w, a10);
                a11 = fmaf(p[(i+1)*6 + j + 1], w, a11);
            }
        float r = 0.25f * (fmaxf(a00,0.f) + fmaxf(a01,0.f) +
                           fmaxf(a10,0.f) + fmaxf(a11,0.f));
        g_p1[o*P1_O*P1_O + idx] = r;
    }
}

// ---------------- fused C3 sparse conv 5x5 + ReLU + 2x2 avgpool ----------------
// grid: (ceil(125*125/256), 16) — blockIdx.y = output channel (uniform mask)
__global__ void k_c3p3(const float* __restrict__ W3,
                       const float* __restrict__ b3) {
    int oc = blockIdx.y;
    __shared__ float sw[6*25];
    __shared__ float sb;
    if (threadIdx.x < 150) sw[threadIdx.x] = W3[oc*150 + threadIdx.x];
    if (threadIdx.x == 0)  sb = b3[oc];
    __syncthreads();

    const unsigned MASKS[16] = {
        0x07u, 0x0Eu, 0x1Cu, 0x38u, 0x31u, 0x23u,
        0x0Fu, 0x1Eu, 0x3Cu, 0x39u, 0x33u, 0x27u,
        0x1Bu, 0x36u, 0x2Du, 0x3Fu };
    unsigned mask = MASKS[oc];

    int idx = blockIdx.x * blockDim.x + threadIdx.x;
    if (idx >= P3_O * P3_O) return;
    int py = idx / P3_O, px = idx % P3_O;

    float b = sb;
    float a00 = b, a01 = b, a10 = b, a11 = b;

#pragma unroll
    for (int c = 0; c < 6; c++) {
        if ((mask >> c) & 1u) {           // uniform per block
            float p[36];
            const float* src = g_p1 + c*P1_O*P1_O + (2*py)*P1_O + 2*px;
#pragma unroll
            for (int i = 0; i < 6; i++)
#pragma unroll
                for (int j = 0; j < 6; j++)
                    p[i*6+j] = src[i*P1_O + j];
#pragma unroll
            for (int i = 0; i < 5; i++)
#pragma unroll
                for (int j = 0; j < 5; j++) {
                    float w = sw[c*25 + i*5 + j];
                    a00 = fmaf(p[ i   *6 + j    ], w, a00);
                    a01 = fmaf(p[ i   *6 + j + 1], w, a01);
                    a10 = fmaf(p[(i+1)*6 + j    ], w, a10);
                    a11 = fmaf(p[(i+1)*6 + j + 1], w, a11);
                }
        }
    }
    float r = 0.25f * (fmaxf(a00,0.f) + fmaxf(a01,0.f) +
                       fmaxf(a10,0.f) + fmaxf(a11,0.f));
    g_p3[oc*P3_O*P3_O + idx] = r;
}

// ---------------- C5: 120 x dot(250000), split-K + last-block reduce ----------------
__global__ void k_c5(const float* __restrict__ W5,
                     const float* __restrict__ b5) {
    int o = blockIdx.x;          // 0..119
    int s = blockIdx.y;          // 0..31
    const float4* __restrict__ w = (const float4*)(W5 + (size_t)o * NP3);
    const float4* __restrict__ h = (const float4*)g_p3;
    const int per = (N4P3 + C5_SPLIT - 1) / C5_SPLIT;   // 1954
    int start = s * per;
    int end   = min(start + per, N4P3);
    float acc = 0.0f;
    for (int i = start + threadIdx.x; i < end; i += blockDim.x) {
        float4 a = __ldg(&w[i]);
        float4 b = h[i];
        acc += a.x*b.x + a.y*b.y + a.z*b.z + a.w*b.w;
    }
    __shared__ float red[256];
    red[threadIdx.x] = acc;
    __syncthreads();
#pragma unroll
    for (int st = 128; st > 0; st >>= 1) {
        if (threadIdx.x < st) red[threadIdx.x] += red[threadIdx.x + st];
        __syncthreads();
    }
    __shared__ int slast;
    if (threadIdx.x == 0) {
        g_c5part[o * C5_SPLIT + s] = red[0];
        __threadfence();
        int t = atomicAdd(&g_c5cnt, 1);
        slast = (t == 120*C5_SPLIT - 1);
    }
    __syncthreads();
    if (slast) {                  // last block finalizes (deterministic order)
        int oo = threadIdx.x;
        if (oo < 120) {
            float a = b5[oo];
#pragma unroll
            for (int ss = 0; ss < C5_SPLIT; ss++) a += g_c5part[oo*C5_SPLIT + ss];
            g_c5[oo] = fmaxf(a, 0.0f);
        }
        if (threadIdx.x == 0) g_c5cnt = 0;   // reset for next replay
    }
}

// ---------------- F6: GEMV 98304x120, warp-per-row ----------------
__global__ void k_f6(const float* __restrict__ W6,
                     const float* __restrict__ b6) {
    __shared__ __align__(16) float sc[120];
    if (threadIdx.x < 120) sc[threadIdx.x] = g_c5[threadIdx.x];
    __syncthreads();

    int warp = threadIdx.x >> 5;
    int lane = threadIdx.x & 31;
    int j = blockIdx.x * 8 + warp;
    float acc = 0.0f;
    if (lane < 30) {
        float4 a = __ldg((const float4*)(W6 + (size_t)j * 120) + lane);
        float4 b = ((const float4*)sc)[lane];
        acc = a.x*b.x + a.y*b.y + a.z*b.z + a.w*b.w;
    }
#pragma unroll
    for (int off = 16; off > 0; off >>= 1)
        acc += __shfl_down_sync(0xFFFFFFFFu, acc, off);
    if (lane == 0) g_f6[j] = fmaxf(acc + b6[j], 0.0f);
}

// ---------------- final: GEMV 54x98304, split-K + last-block reduce ----------------
__global__ void k_fin(const float* __restrict__ W7,
                      const float* __restrict__ b7,
                      float* __restrict__ out) {
    int o = blockIdx.x;          // 0..53
    int s = blockIdx.y;          // 0..63
    const float4* __restrict__ w = (const float4*)(W7 + (size_t)o * F6OUT);
    const float4* __restrict__ h = (const float4*)g_f6;
    const int n4 = F6OUT / 4;                     // 24576
    const int per = n4 / FIN_SPLIT;               // 384
    int start = s * per;
    float acc = 0.0f;
    for (int i = start + threadIdx.x; i < start + per; i += blockDim.x) {
        float4 a = __ldg(&w[i]);
        float4 b = h[i];
        acc += a.x*b.x + a.y*b.y + a.z*b.z + a.w*b.w;
    }
    __shared__ float red[256];
    red[threadIdx.x] = acc;
    __syncthreads();
#pragma unroll
    for (int st = 128; st > 0; st >>= 1) {
        if (threadIdx.x < st) red[threadIdx.x] += red[threadIdx.x + st];
        __syncthreads();
    }
    __shared__ int slast;
    if (threadIdx.x == 0) {
        g_fpart[o * FIN_SPLIT + s] = red[0];
        __threadfence();
        int t = atomicAdd(&g_fincnt, 1);
        slast = (t == NOUT*FIN_SPLIT - 1);
    }
    __syncthreads();
    if (slast) {
        int oo = threadIdx.x;
        if (oo < NOUT) {
            float a = b7[oo];
#pragma unroll
            for (int ss = 0; ss < FIN_SPLIT; ss++) a += g_fpart[oo*FIN_SPLIT + ss];
            out[oo] = a;
        }
        if (threadIdx.x == 0) g_fincnt = 0;
    }
}

// ---------------- launch ----------------
extern "C" void kernel_launch(void* const* d_in, const int* in_sizes, int n_in,
                              void* d_out, int out_size) {
    const float* x  = (const float*)d_in[0];
    const float* W1 = (const float*)d_in[1];
    const float* b1 = (const float*)d_in[2];
    const float* W3 = (const float*)d_in[3];
    const float* b3 = (const float*)d_in[4];
    const float* W5 = (const float*)d_in[5];
    const float* b5 = (const float*)d_in[6];
    const float* W6 = (const float*)d_in[7];
    const float* b6 = (const float*)d_in[8];
    const float* W7 = (const float*)d_in[9];
    const float* b7 = (const float*)d_in[10];
    float* out = (float*)d_out;

    k_c1p1<<<(P1_O*P1_O + 255)/256, 256>>>(x, W1, b1);
    k_c3p3<<<dim3((P3_O*P3_O + 255)/256, 16), 256>>>(W3, b3);
    k_c5<<<dim3(120, C5_SPLIT), 256>>>(W5, b5);
    k_f6<<<F6OUT/8, 256>>>(W6, b6);
    k_fin<<<dim3(NOUT, FIN_SPLIT), 256>>>(W7, b7, out);
}

// round 3
// speedup vs baseline: 1.3453x; 1.1982x over previous
#include <cuda_runtime.h>
#include <cuda_bf16.h>

// ---------------- geometry ----------------
#define L0      512
#define P1_O    254          // pooled conv1 output
#define P3_O    125
#define NP3     (16*125*125) // 250000
#define N4P3    (NP3/4)      // 62500 float4
#define F6OUT   98304
#define NOUT    54
#define C5_SPLIT 32
#define FIN_SPLIT 64

// ---------------- scratch (device globals, no allocation) ----------------
__device__ __align__(16) float g_p1[6*P1_O*P1_O];
__device__ __align__(16) float g_p3[NP3];
__device__ __align__(16) float g_c5part[120*C5_SPLIT];
__device__ __align__(16) float g_c5[120];
__device__ __align__(16) float g_f6[F6OUT];
__device__ __align__(16) float g_fpart[NOUT*FIN_SPLIT];
__device__ int g_c5cnt;   // zero-init; self-resetting
__device__ int g_fincnt;  // zero-init; self-resetting

// ---------------- fused C1 conv 5x5 + ReLU + 2x2 avgpool ----------------
__global__ void k_c1p1(const float* __restrict__ x,
                       const float* __restrict__ W1,
                       const float* __restrict__ b1) {
    __shared__ float sw[6*25];
    __shared__ float sb[6];
    if (threadIdx.x < 150) sw[threadIdx.x] = W1[threadIdx.x];
    if (threadIdx.x < 6)   sb[threadIdx.x] = b1[threadIdx.x];
    __syncthreads();

    int idx = blockIdx.x * blockDim.x + threadIdx.x;
    if (idx >= P1_O * P1_O) return;
    int py = idx / P1_O, px = idx % P1_O;

    float p[36];
#pragma unroll
    for (int i = 0; i < 6; i++)
#pragma unroll
        for (int j = 0; j < 6; j++)
            p[i*6+j] = x[(2*py + i)*L0 + 2*px + j];

#pragma unroll
    for (int o = 0; o < 6; o++) {
        float b = sb[o];
        float a00 = b, a01 = b, a10 = b, a11 = b;
#pragma unroll
        for (int i = 0; i < 5; i++)
#pragma unroll
            for (int j = 0; j < 5; j++) {
                float w = sw[o*25 + i*5 + j];
                a00 = fmaf(p[ i   *6 + j    ], w, a00);
                a01 = fmaf(p[ i   *6 + j + 1], w, a01);
                a10 = fmaf(p[(i+1)*6 + j    ], w, a10);
                a11 = fmaf(p[(i+1)*6 + j + 1], w, a11);
            }
        float r = 0.25f * (fmaxf(a00,0.f) + fmaxf(a01,0.f) +
                           fmaxf(a10,0.f) + fmaxf(a11,0.f));
        g_p1[o*P1_O*P1_O + idx] = r;
    }
}

// ---------------- fused C3 sparse conv 5x5 + ReLU + 2x2 avgpool ----------------
__global__ void k_c3p3(const float* __restrict__ W3,
                       const float* __restrict__ b3) {
    int oc = blockIdx.y;
    __shared__ float sw[6*25];
    __shared__ float sb;
    if (threadIdx.x < 150) sw[threadIdx.x] = W3[oc*150 + threadIdx.x];
    if (threadIdx.x == 0)  sb = b3[oc];
    __syncthreads();

    const unsigned MASKS[16] = {
        0x07u, 0x0Eu, 0x1Cu, 0x38u, 0x31u, 0x23u,
        0x0Fu, 0x1Eu, 0x3Cu, 0x39u, 0x33u, 0x27u,
        0x1Bu, 0x36u, 0x2Du, 0x3Fu };
    unsigned mask = MASKS[oc];

    int idx = blockIdx.x * blockDim.x + threadIdx.x;
    if (idx >= P3_O * P3_O) return;
    int py = idx / P3_O, px = idx % P3_O;

    float b = sb;
    float a00 = b, a01 = b, a10 = b, a11 = b;

#pragma unroll
    for (int c = 0; c < 6; c++) {
        if ((mask >> c) & 1u) {           // uniform per block
            float p[36];
            const float* src = g_p1 + c*P1_O*P1_O + (2*py)*P1_O + 2*px;
#pragma unroll
            for (int i = 0; i < 6; i++)
#pragma unroll
                for (int j = 0; j < 6; j++)
                    p[i*6+j] = src[i*P1_O + j];
#pragma unroll
            for (int i = 0; i < 5; i++)
#pragma unroll
                for (int j = 0; j < 5; j++) {
                    float w = sw[c*25 + i*5 + j];
                    a00 = fmaf(p[ i   *6 + j    ], w, a00);
                    a01 = fmaf(p[ i   *6 + j + 1], w, a01);
                    a10 = fmaf(p[(i+1)*6 + j    ], w, a10);
                    a11 = fmaf(p[(i+1)*6 + j + 1], w, a11);
                }
        }
    }
    float r = 0.25f * (fmaxf(a00,0.f) + fmaxf(a01,0.f) +
                       fmaxf(a10,0.f) + fmaxf(a11,0.f));
    g_p3[oc*P3_O*P3_O + idx] = r;
}

// ---------------- C5: 120 x dot(250000), split-K + last-block reduce ----------------
__global__ void k_c5(const float* __restrict__ W5,
                     const float* __restrict__ b5) {
    int o = blockIdx.x;          // 0..119
    int s = blockIdx.y;          // 0..31
    const float4* __restrict__ w = (const float4*)(W5 + (size_t)o * NP3);
    const float4* __restrict__ h = (const float4*)g_p3;
    const int per = (N4P3 + C5_SPLIT - 1) / C5_SPLIT;   // 1954
    int start = s * per;
    int end   = min(start + per, N4P3);

    float acc0 = 0.0f, acc1 = 0.0f;
    int base = start + threadIdx.x;
#pragma unroll
    for (int it = 0; it < 8; it++) {          // 8*256 = 2048 >= 1954
        int i = base + it * 256;
        if (i < end) {
            float4 a = __ldg(&w[i]);
            float4 b = h[i];
            float d = a.x*b.x + a.y*b.y + a.z*b.z + a.w*b.w;
            if (it & 1) acc1 += d; else acc0 += d;
        }
    }
    float acc = acc0 + acc1;

    __shared__ float red[256];
    red[threadIdx.x] = acc;
    __syncthreads();
#pragma unroll
    for (int st = 128; st > 0; st >>= 1) {
        if (threadIdx.x < st) red[threadIdx.x] += red[threadIdx.x + st];
        __syncthreads();
    }
    __shared__ int slast;
    if (threadIdx.x == 0) {
        g_c5part[o * C5_SPLIT + s] = red[0];
        __threadfence();
        int t = atomicAdd(&g_c5cnt, 1);
        slast = (t == 120*C5_SPLIT - 1);
    }
    __syncthreads();
    if (slast) {
        int oo = threadIdx.x;
        if (oo < 120) {
            float a = b5[oo];
#pragma unroll
            for (int ss = 0; ss < C5_SPLIT; ss++) a += g_c5part[oo*C5_SPLIT + ss];
            g_c5[oo] = fmaxf(a, 0.0f);
        }
        if (threadIdx.x == 0) g_c5cnt = 0;
    }
}

// ---------------- F6: GEMV 98304x120, 8 rows/warp, quad-reduction ----------------
// warp: lane = (rowInWarp = lane>>2, quad = lane&3); 8 independent loads/lane
__global__ void k_f6(const float* __restrict__ W6,
                     const float* __restrict__ b6) {
    __shared__ __align__(16) float sc[120];
    if (threadIdx.x < 120) sc[threadIdx.x] = g_c5[threadIdx.x];
    __syncthreads();

    int warp = threadIdx.x >> 5;
    int lane = threadIdx.x & 31;
    int quad = lane & 3;
    int row  = (blockIdx.x * 8 + warp) * 8 + (lane >> 2);

    const float4* __restrict__ w  = (const float4*)(W6 + (size_t)row * 120);
    const float4* __restrict__ s4 = (const float4*)sc;

    float acc0 = 0.0f, acc1 = 0.0f;
#pragma unroll
    for (int it = 0; it < 8; it++) {
        int k = quad + it * 4;
        if (k < 30) {
            float4 a = __ldg(&w[k]);
            float4 b = s4[k];
            float d = a.x*b.x + a.y*b.y + a.z*b.z + a.w*b.w;
            if (it & 1) acc1 += d; else acc0 += d;
        }
    }
    float acc = acc0 + acc1;
    acc += __shfl_xor_sync(0xFFFFFFFFu, acc, 1);
    acc += __shfl_xor_sync(0xFFFFFFFFu, acc, 2);
    if (quad == 0)
        g_f6[row] = fmaxf(acc + __ldg(&b6[row]), 0.0f);
}

// ---------------- final: GEMV 54x98304, split-K + last-block reduce ----------------
__global__ void k_fin(const float* __restrict__ W7,
                      const float* __restrict__ b7,
                      float* __restrict__ out) {
    int o = blockIdx.x;          // 0..53
    int s = blockIdx.y;          // 0..63
    const float4* __restrict__ w = (const float4*)(W7 + (size_t)o * F6OUT);
    const float4* __restrict__ h = (const float4*)g_f6;
    const int per = (F6OUT/4) / FIN_SPLIT;        // 384
    int start = s * per;

    float acc = 0.0f;
    int i = start + threadIdx.x;                  // 384 elems, 256 threads: 2 iters
    {
        float4 a = __ldg(&w[i]);
        float4 b = h[i];
        acc += a.x*b.x + a.y*b.y + a.z*b.z + a.w*b.w;
    }
    if (threadIdx.x < per - 256) {
        int j = i + 256;
        float4 a = __ldg(&w[j]);
        float4 b = h[j];
        acc += a.x*b.x + a.y*b.y + a.z*b.z + a.w*b.w;
    }

    __shared__ float red[256];
    red[threadIdx.x] = acc;
    __syncthreads();
#pragma unroll
    for (int st = 128; st > 0; st >>= 1) {
        if (threadIdx.x < st) red[threadIdx.x] += red[threadIdx.x + st];
        __syncthreads();
    }
    __shared__ int slast;
    if (threadIdx.x == 0) {
        g_fpart[o * FIN_SPLIT + s] = red[0];
        __threadfence();
        int t = atomicAdd(&g_fincnt, 1);
        slast = (t == NOUT*FIN_SPLIT - 1);
    }
    __syncthreads();
    if (slast) {
        int oo = threadIdx.x;
        if (oo < NOUT) {
            float a = b7[oo];
#pragma unroll
            for (int ss = 0; ss < FIN_SPLIT; ss++) a += g_fpart[oo*FIN_SPLIT + ss];
            out[oo] = a;
        }
        if (threadIdx.x == 0) g_fincnt = 0;
    }
}

// ---------------- launch ----------------
extern "C" void kernel_launch(void* const* d_in, const int* in_sizes, int n_in,
                              void* d_out, int out_size) {
    const float* x  = (const float*)d_in[0];
    const float* W1 = (const float*)d_in[1];
    const float* b1 = (const float*)d_in[2];
    const float* W3 = (const float*)d_in[3];
    const float* b3 = (const float*)d_in[4];
    const float* W5 = (const float*)d_in[5];
    const float* b5 = (const float*)d_in[6];
    const float* W6 = (const float*)d_in[7];
    const float* b6 = (const float*)d_in[8];
    const float* W7 = (const float*)d_in[9];
    const float* b7 = (const float*)d_in[10];
    float* out = (float*)d_out;

    k_c1p1<<<(P1_O*P1_O + 255)/256, 256>>>(x, W1, b1);
    k_c3p3<<<dim3((P3_O*P3_O + 255)/256, 16), 256>>>(W3, b3);
    k_c5<<<dim3(120, C5_SPLIT), 256>>>(W5, b5);
    k_f6<<<F6OUT/64, 256>>>(W6, b6);
    k_fin<<<dim3(NOUT, FIN_SPLIT), 256>>>(W7, b7, out);
}

// round 4
// speedup vs baseline: 1.5209x; 1.1305x over previous
#include <cuda_runtime.h>
#include <cuda_bf16.h>

// ---------------- geometry ----------------
#define L0      512
#define P1_O    254
#define P3_O    125
#define NP3     (16*125*125) // 250000
#define N4P3    (NP3/4)      // 62500 float4
#define F6OUT   98304
#define NOUT    54
#define C5_NS   20           // c5 K-chunks (62500/20 = 3125 exact)
#define FIN_NS  12           // fin K-chunks (24576/12 = 2048 exact)

// ---------------- scratch ----------------
__device__ __align__(16) float g_p1[6*P1_O*P1_O];
__device__ __align__(16) float g_p3[NP3];
__device__ __align__(16) float g_c5part[120*C5_NS];
__device__ __align__(16) float g_c5[120];
__device__ __align__(16) float g_f6[F6OUT];
__device__ __align__(16) float g_fpart[NOUT*FIN_NS];
__device__ int g_c5cnt;
__device__ int g_fincnt;

__device__ __forceinline__ float dot4(float4 a, float4 b) {
    return a.x*b.x + a.y*b.y + a.z*b.z + a.w*b.w;
}

// ---------------- fused C1 conv 5x5 + ReLU + 2x2 avgpool ----------------
__global__ void k_c1p1(const float* __restrict__ x,
                       const float* __restrict__ W1,
                       const float* __restrict__ b1) {
    __shared__ float sw[6*25];
    __shared__ float sb[6];
    if (threadIdx.x < 150) sw[threadIdx.x] = W1[threadIdx.x];
    if (threadIdx.x < 6)   sb[threadIdx.x] = b1[threadIdx.x];
    __syncthreads();

    int idx = blockIdx.x * blockDim.x + threadIdx.x;
    if (idx >= P1_O * P1_O) return;
    int py = idx / P1_O, px = idx % P1_O;

    float p[36];
#pragma unroll
    for (int i = 0; i < 6; i++)
#pragma unroll
        for (int j = 0; j < 6; j++)
            p[i*6+j] = x[(2*py + i)*L0 + 2*px + j];

#pragma unroll
    for (int o = 0; o < 6; o++) {
        float b = sb[o];
        float a00 = b, a01 = b, a10 = b, a11 = b;
#pragma unroll
        for (int i = 0; i < 5; i++)
#pragma unroll
            for (int j = 0; j < 5; j++) {
                float w = sw[o*25 + i*5 + j];
                a00 = fmaf(p[ i   *6 + j    ], w, a00);
                a01 = fmaf(p[ i   *6 + j + 1], w, a01);
                a10 = fmaf(p[(i+1)*6 + j    ], w, a10);
                a11 = fmaf(p[(i+1)*6 + j + 1], w, a11);
            }
        g_p1[o*P1_O*P1_O + idx] = 0.25f * (fmaxf(a00,0.f) + fmaxf(a01,0.f) +
                                           fmaxf(a10,0.f) + fmaxf(a11,0.f));
    }
}

// ---------------- fused C3 sparse conv 5x5 + ReLU + 2x2 avgpool ----------------
__global__ void k_c3p3(const float* __restrict__ W3,
                       const float* __restrict__ b3) {
    int oc = blockIdx.y;
    __shared__ float sw[6*25];
    __shared__ float sb;
    if (threadIdx.x < 150) sw[threadIdx.x] = W3[oc*150 + threadIdx.x];
    if (threadIdx.x == 0)  sb = b3[oc];
    __syncthreads();

    const unsigned MASKS[16] = {
        0x07u, 0x0Eu, 0x1Cu, 0x38u, 0x31u, 0x23u,
        0x0Fu, 0x1Eu, 0x3Cu, 0x39u, 0x33u, 0x27u,
        0x1Bu, 0x36u, 0x2Du, 0x3Fu };
    unsigned mask = MASKS[oc];

    int idx = blockIdx.x * blockDim.x + threadIdx.x;
    if (idx >= P3_O * P3_O) return;
    int py = idx / P3_O, px = idx % P3_O;

    float b = sb;
    float a00 = b, a01 = b, a10 = b, a11 = b;

#pragma unroll
    for (int c = 0; c < 6; c++) {
        if ((mask >> c) & 1u) {
            float p[36];
            const float* src = g_p1 + c*P1_O*P1_O + (2*py)*P1_O + 2*px;
#pragma unroll
            for (int i = 0; i < 6; i++)
#pragma unroll
                for (int j = 0; j < 6; j++)
                    p[i*6+j] = src[i*P1_O + j];
#pragma unroll
            for (int i = 0; i < 5; i++)
#pragma unroll
                for (int j = 0; j < 5; j++) {
                    float w = sw[c*25 + i*5 + j];
                    a00 = fmaf(p[ i   *6 + j    ], w, a00);
                    a01 = fmaf(p[ i   *6 + j + 1], w, a01);
                    a10 = fmaf(p[(i+1)*6 + j    ], w, a10);
                    a11 = fmaf(p[(i+1)*6 + j + 1], w, a11);
                }
        }
    }
    g_p3[oc*P3_O*P3_O + idx] = 0.25f * (fmaxf(a00,0.f) + fmaxf(a01,0.f) +
                                        fmaxf(a10,0.f) + fmaxf(a11,0.f));
}

// ---------------- C5: 4 outputs/block, split-K, last-block reduce ----------------
// grid (30, C5_NS), block 256. Each block: chunk of 3125 float4 x 4 output rows.
__global__ void __launch_bounds__(256, 4) k_c5(const float* __restrict__ W5,
                                               const float* __restrict__ b5) {
    int og = blockIdx.x;          // 0..29  -> outputs 4*og .. 4*og+3
    int s  = blockIdx.y;          // 0..C5_NS-1
    const int per = N4P3 / C5_NS; // 3125
    int start = s * per, end = start + per;

    const float4* __restrict__ h  = (const float4*)g_p3;
    const float4* __restrict__ w0 = (const float4*)(W5 + (size_t)(4*og+0) * NP3);
    const float4* __restrict__ w1 = (const float4*)(W5 + (size_t)(4*og+1) * NP3);
    const float4* __restrict__ w2 = (const float4*)(W5 + (size_t)(4*og+2) * NP3);
    const float4* __restrict__ w3 = (const float4*)(W5 + (size_t)(4*og+3) * NP3);

    float a0 = 0.f, a1 = 0.f, a2 = 0.f, a3 = 0.f;
#pragma unroll 2
    for (int i = start + threadIdx.x; i < end; i += 256) {
        float4 hv = h[i];
        float4 x0 = __ldcs(&w0[i]);
        float4 x1 = __ldcs(&w1[i]);
        float4 x2 = __ldcs(&w2[i]);
        float4 x3 = __ldcs(&w3[i]);
        a0 += dot4(x0, hv);
        a1 += dot4(x1, hv);
        a2 += dot4(x2, hv);
        a3 += dot4(x3, hv);
    }

    __shared__ float red[4*256];
    red[0*256 + threadIdx.x] = a0;
    red[1*256 + threadIdx.x] = a1;
    red[2*256 + threadIdx.x] = a2;
    red[3*256 + threadIdx.x] = a3;
    __syncthreads();
    // 256 threads reduce 4 rows of 256: thread t handles row t>>6, 4 strided sums then warp
    {
        int r = threadIdx.x >> 6;          // 0..3
        int c = threadIdx.x & 63;          // 0..63
        float v = red[r*256 + c] + red[r*256 + c + 64] +
                  red[r*256 + c + 128] + red[r*256 + c + 192];
#pragma unroll
        for (int off = 16; off > 0; off >>= 1)
            v += __shfl_down_sync(0xFFFFFFFFu, v, off);
        __syncthreads();
        if ((c & 31) == 0) red[r*2 + (c >> 5)] = v;   // two partials per row
        __syncthreads();
        if (threadIdx.x < 4)
            g_c5part[(4*og + threadIdx.x) * C5_NS + s] =
                red[threadIdx.x*2] + red[threadIdx.x*2 + 1];
    }

    __shared__ int slast;
    __syncthreads();
    if (threadIdx.x == 0) {
        __threadfence();
        int t = atomicAdd(&g_c5cnt, 1);
        slast = (t == 30*C5_NS - 1);
    }
    __syncthreads();
    if (slast) {
        int oo = threadIdx.x;
        if (oo < 120) {
            float a = b5[oo];
#pragma unroll
            for (int ss = 0; ss < C5_NS; ss++) a += g_c5part[oo*C5_NS + ss];
            g_c5[oo] = fmaxf(a, 0.0f);
        }
        if (threadIdx.x == 0) g_c5cnt = 0;
    }
}

// ---------------- F6: GEMV 98304x120 ----------------
// grid 512 x 256 thr; each block: 3 groups of 64 rows (exact). Warp: 8 rows,
// lane=(row=lane>>2, quad=lane&3), 8 predicated float4 loads per lane.
__global__ void __launch_bounds__(256, 4) k_f6(const float* __restrict__ W6,
                                               const float* __restrict__ b6) {
    __shared__ __align__(16) float sc[120];
    if (threadIdx.x < 120) sc[threadIdx.x] = g_c5[threadIdx.x];
    __syncthreads();

    int warp = threadIdx.x >> 5;
    int lane = threadIdx.x & 31;
    int quad = lane & 3;
    const float4* __restrict__ s4 = (const float4*)sc;

#pragma unroll
    for (int g = 0; g < 3; g++) {
        int row = blockIdx.x * 192 + g * 64 + warp * 8 + (lane >> 2);
        const float4* __restrict__ w = (const float4*)(W6 + (size_t)row * 120);
        float acc0 = 0.f, acc1 = 0.f;
#pragma unroll
        for (int it = 0; it < 8; it++) {
            int k = quad + it * 4;
            if (k < 30) {
                float4 a = __ldcs(&w[k]);
                float4 b = s4[k];
                float d = dot4(a, b);
                if (it & 1) acc1 += d; else acc0 += d;
            }
        }
        float acc = acc0 + acc1;
        acc += __shfl_xor_sync(0xFFFFFFFFu, acc, 1);
        acc += __shfl_xor_sync(0xFFFFFFFFu, acc, 2);
        if (quad == 0)
            g_f6[row] = fmaxf(acc + __ldg(&b6[row]), 0.0f);
    }
}

// ---------------- final: GEMV 54x98304, split-K, last-block reduce ----------------
// grid (54, FIN_NS), block 256; 2048 float4 per chunk = exactly 8 iters/thread.
__global__ void __launch_bounds__(256, 4) k_fin(const float* __restrict__ W7,
                                                const float* __restrict__ b7,
                                                float* __restrict__ out) {
    int o = blockIdx.x;
    int s = blockIdx.y;
    const float4* __restrict__ w = (const float4*)(W7 + (size_t)o * F6OUT);
    const float4* __restrict__ h = (const float4*)g_f6;
    const int per = (F6OUT/4) / FIN_NS;    // 2048
    int base = s * per + threadIdx.x;

    float acc0 = 0.f, acc1 = 0.f;
#pragma unroll
    for (int it = 0; it < 8; it++) {
        int i = base + it * 256;
        float4 a = __ldcs(&w[i]);
        float4 b = h[i];
        float d = dot4(a, b);
        if (it & 1) acc1 += d; else acc0 += d;
    }
    float acc = acc0 + acc1;

    __shared__ float red[256];
    red[threadIdx.x] = acc;
    __syncthreads();
#pragma unroll
    for (int st = 128; st > 0; st >>= 1) {
        if (threadIdx.x < st) red[threadIdx.x] += red[threadIdx.x + st];
        __syncthreads();
    }
    __shared__ int slast;
    if (threadIdx.x == 0) {
        g_fpart[o * FIN_NS + s] = red[0];
        __threadfence();
        int t = atomicAdd(&g_fincnt, 1);
        slast = (t == NOUT*FIN_NS - 1);
    }
    __syncthreads();
    if (slast) {
        int oo = threadIdx.x;
        if (oo < NOUT) {
            float a = b7[oo];
#pragma unroll
            for (int ss = 0; ss < FIN_NS; ss++) a += g_fpart[oo*FIN_NS + ss];
            out[oo] = a;
        }
        if (threadIdx.x == 0) g_fincnt = 0;
    }
}

// ---------------- launch ----------------
extern "C" void kernel_launch(void* const* d_in, const int* in_sizes, int n_in,
                              void* d_out, int out_size) {
    const float* x  = (const float*)d_in[0];
    const float* W1 = (const float*)d_in[1];
    const float* b1 = (const float*)d_in[2];
    const float* W3 = (const float*)d_in[3];
    const float* b3 = (const float*)d_in[4];
    const float* W5 = (const float*)d_in[5];
    const float* b5 = (const float*)d_in[6];
    const float* W6 = (const float*)d_in[7];
    const float* b6 = (const float*)d_in[8];
    const float* W7 = (const float*)d_in[9];
    const float* b7 = (const float*)d_in[10];
    float* out = (float*)d_out;

    k_c1p1<<<(P1_O*P1_O + 255)/256, 256>>>(x, W1, b1);
    k_c3p3<<<dim3((P3_O*P3_O + 255)/256, 16), 256>>>(W3, b3);
    k_c5<<<dim3(30, C5_NS), 256>>>(W5, b5);
    k_f6<<<F6OUT/192, 256>>>(W6, b6);
    k_fin<<<dim3(NOUT, FIN_NS), 256>>>(W7, b7, out);
}

// round 5
// speedup vs baseline: 1.7092x; 1.1238x over previous
#include <cuda_runtime.h>
#include <cuda_bf16.h>

// ---------------- geometry ----------------
#define L0      512
#define P1_O    254
#define P3_O    125
#define NP3     (16*125*125) // 250000
#define N4P3    (NP3/4)      // 62500 float4
#define F6OUT   98304
#define NOUT    54
#define C5_NS   25           // 62500/25 = 2500 exact
#define FIN_NS  12           // 24576/12 = 2048 exact

// ---------------- scratch ----------------
__device__ __align__(16) float g_p1[6*P1_O*P1_O];
__device__ __align__(16) float g_p3[NP3];
__device__ __align__(16) float g_c5part[120*C5_NS];
__device__ __align__(16) float g_c5[120];
__device__ __align__(16) float g_f6[F6OUT];
__device__ __align__(16) float g_fpart[NOUT*FIN_NS];
__device__ int g_c5cnt;
__device__ int g_fincnt;

__device__ __forceinline__ float dot4(float4 a, float4 b) {
    return a.x*b.x + a.y*b.y + a.z*b.z + a.w*b.w;
}

// ---------------- fused C1 conv 5x5 + ReLU + 2x2 avgpool ----------------
__global__ void k_c1p1(const float* __restrict__ x,
                       const float* __restrict__ W1,
                       const float* __restrict__ b1) {
    __shared__ float sw[6*25];
    __shared__ float sb[6];
    if (threadIdx.x < 150) sw[threadIdx.x] = W1[threadIdx.x];
    if (threadIdx.x < 6)   sb[threadIdx.x] = b1[threadIdx.x];
    __syncthreads();

    int idx = blockIdx.x * blockDim.x + threadIdx.x;
    if (idx >= P1_O * P1_O) return;
    int py = idx / P1_O, px = idx % P1_O;

    float p[36];
#pragma unroll
    for (int i = 0; i < 6; i++)
#pragma unroll
        for (int j = 0; j < 6; j++)
            p[i*6+j] = x[(2*py + i)*L0 + 2*px + j];

#pragma unroll
    for (int o = 0; o < 6; o++) {
        float b = sb[o];
        float a00 = b, a01 = b, a10 = b, a11 = b;
#pragma unroll
        for (int i = 0; i < 5; i++)
#pragma unroll
            for (int j = 0; j < 5; j++) {
                float w = sw[o*25 + i*5 + j];
                a00 = fmaf(p[ i   *6 + j    ], w, a00);
                a01 = fmaf(p[ i   *6 + j + 1], w, a01);
                a10 = fmaf(p[(i+1)*6 + j    ], w, a10);
                a11 = fmaf(p[(i+1)*6 + j + 1], w, a11);
            }
        g_p1[o*P1_O*P1_O + idx] = 0.25f * (fmaxf(a00,0.f) + fmaxf(a01,0.f) +
                                           fmaxf(a10,0.f) + fmaxf(a11,0.f));
    }
}

// ---------------- fused C3 sparse conv 5x5 + ReLU + 2x2 avgpool ----------------
__global__ void k_c3p3(const float* __restrict__ W3,
                       const float* __restrict__ b3) {
    int oc = blockIdx.y;
    __shared__ float sw[6*25];
    __shared__ float sb;
    if (threadIdx.x < 150) sw[threadIdx.x] = W3[oc*150 + threadIdx.x];
    if (threadIdx.x == 0)  sb = b3[oc];
    __syncthreads();

    const unsigned MASKS[16] = {
        0x07u, 0x0Eu, 0x1Cu, 0x38u, 0x31u, 0x23u,
        0x0Fu, 0x1Eu, 0x3Cu, 0x39u, 0x33u, 0x27u,
        0x1Bu, 0x36u, 0x2Du, 0x3Fu };
    unsigned mask = MASKS[oc];

    int idx = blockIdx.x * blockDim.x + threadIdx.x;
    if (idx >= P3_O * P3_O) return;
    int py = idx / P3_O, px = idx % P3_O;

    float b = sb;
    float a00 = b, a01 = b, a10 = b, a11 = b;

#pragma unroll
    for (int c = 0; c < 6; c++) {
        if ((mask >> c) & 1u) {
            float p[36];
            const float* src = g_p1 + c*P1_O*P1_O + (2*py)*P1_O + 2*px;
#pragma unroll
            for (int i = 0; i < 6; i++)
#pragma unroll
                for (int j = 0; j < 6; j++)
                    p[i*6+j] = src[i*P1_O + j];
#pragma unroll
            for (int i = 0; i < 5; i++)
#pragma unroll
                for (int j = 0; j < 5; j++) {
                    float w = sw[c*25 + i*5 + j];
                    a00 = fmaf(p[ i   *6 + j    ], w, a00);
                    a01 = fmaf(p[ i   *6 + j + 1], w, a01);
                    a10 = fmaf(p[(i+1)*6 + j    ], w, a10);
                    a11 = fmaf(p[(i+1)*6 + j + 1], w, a11);
                }
        }
    }
    g_p3[oc*P3_O*P3_O + idx] = 0.25f * (fmaxf(a00,0.f) + fmaxf(a01,0.f) +
                                        fmaxf(a10,0.f) + fmaxf(a11,0.f));
}

// ---------------- C5: 8 outputs/block, split-K, last-block reduce ----------------
// grid (15, C5_NS), block 256. Each block: chunk of 2500 float4 x 8 output rows.
__global__ void __launch_bounds__(256, 3) k_c5(const float* __restrict__ W5,
                                               const float* __restrict__ b5) {
    int og = blockIdx.x;          // 0..14  -> outputs 8*og .. 8*og+7
    int s  = blockIdx.y;          // 0..C5_NS-1
    const int per = N4P3 / C5_NS; // 2500
    int start = s * per, end = start + per;

    const float4* __restrict__ h = (const float4*)g_p3;
    const float4* w[8];
#pragma unroll
    for (int r = 0; r < 8; r++)
        w[r] = (const float4*)(W5 + (size_t)(8*og + r) * NP3);

    float acc[8];
#pragma unroll
    for (int r = 0; r < 8; r++) acc[r] = 0.f;

#pragma unroll 2
    for (int i = start + threadIdx.x; i < end; i += 256) {
        float4 hv = h[i];
        float4 xv[8];
#pragma unroll
        for (int r = 0; r < 8; r++) xv[r] = __ldcs(&w[r][i]);
#pragma unroll
        for (int r = 0; r < 8; r++) acc[r] += dot4(xv[r], hv);
    }

    __shared__ float red[8*256];
#pragma unroll
    for (int r = 0; r < 8; r++) red[r*256 + threadIdx.x] = acc[r];
    __syncthreads();
    {
        int r = threadIdx.x >> 5;          // 0..7 : one warp per output row
        int c = threadIdx.x & 31;
        float v = 0.f;
#pragma unroll
        for (int k = 0; k < 8; k++) v += red[r*256 + c + 32*k];
#pragma unroll
        for (int off = 16; off > 0; off >>= 1)
            v += __shfl_down_sync(0xFFFFFFFFu, v, off);
        if (c == 0) g_c5part[(8*og + r) * C5_NS + s] = v;
    }

    __shared__ int slast;
    __syncthreads();
    if (threadIdx.x == 0) {
        __threadfence();
        int t = atomicAdd(&g_c5cnt, 1);
        slast = (t == 15*C5_NS - 1);
    }
    __syncthreads();
    if (slast) {
        int oo = threadIdx.x;
        if (oo < 120) {
            float a = b5[oo];
#pragma unroll
            for (int ss = 0; ss < C5_NS; ss++) a += g_c5part[oo*C5_NS + ss];
            g_c5[oo] = fmaxf(a, 0.0f);
        }
        if (threadIdx.x == 0) g_c5cnt = 0;
    }
}

// ---------------- F6: GEMV 98304x120, 8 rows/warp, quad-reduction ----------------
// (round-3 proven config: grid 1536, one group per warp, regs ~44, occ ~57%)
__global__ void k_f6(const float* __restrict__ W6,
                     const float* __restrict__ b6) {
    __shared__ __align__(16) float sc[120];
    if (threadIdx.x < 120) sc[threadIdx.x] = g_c5[threadIdx.x];
    __syncthreads();

    int warp = threadIdx.x >> 5;
    int lane = threadIdx.x & 31;
    int quad = lane & 3;
    int row  = (blockIdx.x * 8 + warp) * 8 + (lane >> 2);

    const float4* __restrict__ w  = (const float4*)(W6 + (size_t)row * 120);
    const float4* __restrict__ s4 = (const float4*)sc;

    float acc0 = 0.0f, acc1 = 0.0f;
#pragma unroll
    for (int it = 0; it < 8; it++) {
        int k = quad + it * 4;
        if (k < 30) {
            float4 a = __ldg(&w[k]);
            float4 b = s4[k];
            float d = dot4(a, b);
            if (it & 1) acc1 += d; else acc0 += d;
        }
    }
    float acc = acc0 + acc1;
    acc += __shfl_xor_sync(0xFFFFFFFFu, acc, 1);
    acc += __shfl_xor_sync(0xFFFFFFFFu, acc, 2);
    if (quad == 0)
        g_f6[row] = fmaxf(acc + __ldg(&b6[row]), 0.0f);
}

// ---------------- final: GEMV 54x98304, split-K, last-block reduce ----------------
__global__ void __launch_bounds__(256, 4) k_fin(const float* __restrict__ W7,
                                                const float* __restrict__ b7,
                                                float* __restrict__ out) {
    int o = blockIdx.x;
    int s = blockIdx.y;
    const float4* __restrict__ w = (const float4*)(W7 + (size_t)o * F6OUT);
    const float4* __restrict__ h = (const float4*)g_f6;
    const int per = (F6OUT/4) / FIN_NS;    // 2048
    int base = s * per + threadIdx.x;

    float acc0 = 0.f, acc1 = 0.f;
#pragma unroll
    for (int it = 0; it < 8; it++) {
        int i = base + it * 256;
        float4 a = __ldcs(&w[i]);
        float4 b = h[i];
        float d = dot4(a, b);
        if (it & 1) acc1 += d; else acc0 += d;
    }
    float acc = acc0 + acc1;

    __shared__ float red[256];
    red[threadIdx.x] = acc;
    __syncthreads();
#pragma unroll
    for (int st = 128; st > 0; st >>= 1) {
        if (threadIdx.x < st) red[threadIdx.x] += red[threadIdx.x + st];
        __syncthreads();
    }
    __shared__ int slast;
    if (threadIdx.x == 0) {
        g_fpart[o * FIN_NS + s] = red[0];
        __threadfence();
        int t = atomicAdd(&g_fincnt, 1);
        slast = (t == NOUT*FIN_NS - 1);
    }
    __syncthreads();
    if (slast) {
        int oo = threadIdx.x;
        if (oo < NOUT) {
            float a = b7[oo];
#pragma unroll
            for (int ss = 0; ss < FIN_NS; ss++) a += g_fpart[oo*FIN_NS + ss];
            out[oo] = a;
        }
        if (threadIdx.x == 0) g_fincnt = 0;
    }
}

// ---------------- launch ----------------
extern "C" void kernel_launch(void* const* d_in, const int* in_sizes, int n_in,
                              void* d_out, int out_size) {
    const float* x  = (const float*)d_in[0];
    const float* W1 = (const float*)d_in[1];
    const float* b1 = (const float*)d_in[2];
    const float* W3 = (const float*)d_in[3];
    const float* b3 = (const float*)d_in[4];
    const float* W5 = (const float*)d_in[5];
    const float* b5 = (const float*)d_in[6];
    const float* W6 = (const float*)d_in[7];
    const float* b6 = (const float*)d_in[8];
    const float* W7 = (const float*)d_in[9];
    const float* b7 = (const float*)d_in[10];
    float* out = (float*)d_out;

    k_c1p1<<<(P1_O*P1_O + 255)/256, 256>>>(x, W1, b1);
    k_c3p3<<<dim3((P3_O*P3_O + 255)/256, 16), 256>>>(W3, b3);
    k_c5<<<dim3(15, C5_NS), 256>>>(W5, b5);
    k_f6<<<F6OUT/64, 256>>>(W6, b6);
    k_fin<<<dim3(NOUT, FIN_NS), 256>>>(W7, b7, out);
}